// round 2
// baseline (speedup 1.0000x reference)
#include <cuda_runtime.h>
#include <cuda_bf16.h>
#include <cstdint>

#define N_USERS 100000
#define M_ITEMS 50000
#define N_NODES (N_USERS + M_ITEMS)   // 150000
#define N_EDGES 6000000
#define DIM 64
#define N_ELEMS ((size_t)N_NODES * DIM)   // 9,600,000 floats

// Ping-pong node feature buffers (38.4 MB each). __device__ globals: no allocation.
__device__ float g_h[N_ELEMS];
__device__ float g_hn[N_ELEMS];

// ---------------------------------------------------------------------------
// init: h = concat(user_emb, item_emb); acc (d_out) = same
// ---------------------------------------------------------------------------
__global__ void init_kernel(const float* __restrict__ user_emb,
                            const float* __restrict__ item_emb,
                            float* __restrict__ h,
                            float* __restrict__ acc) {
    size_t i = (size_t)blockIdx.x * blockDim.x + threadIdx.x;   // float4 index
    size_t n4 = N_ELEMS / 4;
    if (i >= n4) return;
    size_t user4 = (size_t)N_USERS * DIM / 4;
    float4 v;
    if (i < user4) v = ((const float4*)user_emb)[i];
    else           v = ((const float4*)item_emb)[i - user4];
    ((float4*)h)[i]   = v;
    ((float4*)acc)[i] = v;
}

// ---------------------------------------------------------------------------
// zero h_next
// ---------------------------------------------------------------------------
__global__ void zero_kernel(float* __restrict__ p) {
    size_t i = (size_t)blockIdx.x * blockDim.x + threadIdx.x;
    if (i >= N_ELEMS / 4) return;
    ((float4*)p)[i] = make_float4(0.f, 0.f, 0.f, 0.f);
}

// ---------------------------------------------------------------------------
// SpMM: for each edge e, h_next[dst[e]] += val[e] * h[src[e]]
// 16 lanes per edge, float4 per lane (64 floats = 256B row).
// Scatter via red.global.add.v4.f32 (vector reduction, no return).
// ---------------------------------------------------------------------------
__global__ void spmm_kernel(const int*   __restrict__ src,
                            const int*   __restrict__ dst,
                            const float* __restrict__ val,
                            const float* __restrict__ h,
                            float*       __restrict__ hn) {
    int e    = blockIdx.x * (blockDim.x >> 4) + (threadIdx.x >> 4);
    int lane = threadIdx.x & 15;
    if (e >= N_EDGES) return;

    int   s = __ldg(src + e);
    int   d = __ldg(dst + e);
    float v = __ldg(val + e);

    const float4* hrow = (const float4*)(h + (size_t)s * DIM) + lane;
    float4 x = __ldg(hrow);
    x.x *= v; x.y *= v; x.z *= v; x.w *= v;

    float* out = hn + (size_t)d * DIM + lane * 4;
    asm volatile("red.global.add.v4.f32 [%0], {%1, %2, %3, %4};"
                 :: "l"(out), "f"(x.x), "f"(x.y), "f"(x.z), "f"(x.w)
                 : "memory");
}

// ---------------------------------------------------------------------------
// acc += hn   (mid layers)
// ---------------------------------------------------------------------------
__global__ void accum_kernel(const float* __restrict__ hn,
                             float* __restrict__ acc) {
    size_t i = (size_t)blockIdx.x * blockDim.x + threadIdx.x;
    if (i >= N_ELEMS / 4) return;
    float4 a = ((const float4*)acc)[i];
    float4 b = ((const float4*)hn)[i];
    a.x += b.x; a.y += b.y; a.z += b.z; a.w += b.w;
    ((float4*)acc)[i] = a;
}

// ---------------------------------------------------------------------------
// acc = (acc + hn) * 0.25   (final layer, folds the /(N_LAYERS+1))
// ---------------------------------------------------------------------------
__global__ void accum_final_kernel(const float* __restrict__ hn,
                                   float* __restrict__ acc) {
    size_t i = (size_t)blockIdx.x * blockDim.x + threadIdx.x;
    if (i >= N_ELEMS / 4) return;
    float4 a = ((const float4*)acc)[i];
    float4 b = ((const float4*)hn)[i];
    a.x = (a.x + b.x) * 0.25f;
    a.y = (a.y + b.y) * 0.25f;
    a.z = (a.z + b.z) * 0.25f;
    a.w = (a.w + b.w) * 0.25f;
    ((float4*)acc)[i] = a;
}

extern "C" void kernel_launch(void* const* d_in, const int* in_sizes, int n_in,
                              void* d_out, int out_size) {
    const float* user_emb = (const float*)d_in[0];
    const float* item_emb = (const float*)d_in[1];
    const int*   edge_src = (const int*)d_in[2];
    const int*   edge_dst = (const int*)d_in[3];
    const float* edge_val = (const float*)d_in[4];
    float* acc = (float*)d_out;

    float *h, *hn;
    cudaGetSymbolAddress((void**)&h,  g_h);
    cudaGetSymbolAddress((void**)&hn, g_hn);

    const int TB = 256;
    const int grid_elem = (int)((N_ELEMS / 4 + TB - 1) / TB);        // 9375
    const int edges_per_block = TB / 16;                              // 16
    const int grid_edge = (N_EDGES + edges_per_block - 1) / edges_per_block;  // 375000

    init_kernel<<<grid_elem, TB>>>(user_emb, item_emb, h, acc);

    // Layer 1
    zero_kernel<<<grid_elem, TB>>>(hn);
    spmm_kernel<<<grid_edge, TB>>>(edge_src, edge_dst, edge_val, h, hn);
    accum_kernel<<<grid_elem, TB>>>(hn, acc);

    // Layer 2 (swap: read hn, write h)
    zero_kernel<<<grid_elem, TB>>>(h);
    spmm_kernel<<<grid_edge, TB>>>(edge_src, edge_dst, edge_val, hn, h);
    accum_kernel<<<grid_elem, TB>>>(h, acc);

    // Layer 3 (swap back: read h, write hn), fold final scale
    zero_kernel<<<grid_elem, TB>>>(hn);
    spmm_kernel<<<grid_edge, TB>>>(edge_src, edge_dst, edge_val, h, hn);
    accum_final_kernel<<<grid_elem, TB>>>(hn, acc);
}

// round 4
// speedup vs baseline: 1.4733x; 1.4733x over previous
#include <cuda_runtime.h>
#include <cuda_bf16.h>
#include <cstdint>

#define N_USERS 100000
#define M_ITEMS 50000
#define N_NODES (N_USERS + M_ITEMS)   // 150000
#define N_EDGES 6000000
#define DIM 64
#define N_ELEMS ((size_t)N_NODES * DIM)   // 9,600,000 floats

#define SCAN_B 1024
#define NB_SCAN ((N_NODES + SCAN_B - 1) / SCAN_B)   // 147

// ---- static scratch (no allocation allowed) --------------------------------
__device__ float g_h [N_ELEMS];      // 38.4 MB  ping
__device__ float g_hn[N_ELEMS];      // 38.4 MB  pong
__device__ int2  g_edges[N_EDGES];   // 48 MB    (src, val_bits) sorted by dst
__device__ int   g_cnt[N_NODES];     // per-node degree
__device__ int   g_off[N_NODES];     // CSR offsets (exclusive scan of cnt)
__device__ int   g_pos[N_NODES];     // scatter cursors
__device__ int   g_part[NB_SCAN];    // per-block partial sums for scan

// ---------------------------------------------------------------------------
// init: h = concat(user_emb, item_emb); acc (d_out) = same. Also zero g_cnt.
// ---------------------------------------------------------------------------
__global__ void init_kernel(const float* __restrict__ user_emb,
                            const float* __restrict__ item_emb,
                            float* __restrict__ h,
                            float* __restrict__ acc) {
    size_t i = (size_t)blockIdx.x * blockDim.x + threadIdx.x;   // float4 index
    size_t n4 = N_ELEMS / 4;
    if (i < n4) {
        size_t user4 = (size_t)N_USERS * DIM / 4;
        float4 v;
        if (i < user4) v = ((const float4*)user_emb)[i];
        else           v = ((const float4*)item_emb)[i - user4];
        ((float4*)h)[i]   = v;
        ((float4*)acc)[i] = v;
    }
    if (i < N_NODES) g_cnt[i] = 0;
}

// ---------------------------------------------------------------------------
// CSR build
// ---------------------------------------------------------------------------
__global__ void hist_kernel(const int* __restrict__ dst) {
    int e = blockIdx.x * blockDim.x + threadIdx.x;
    if (e < N_EDGES) atomicAdd(&g_cnt[dst[e]], 1);
}

__global__ void block_reduce_kernel() {        // g_cnt -> g_part[b]
    __shared__ int sm[SCAN_B];
    int idx = blockIdx.x * SCAN_B + threadIdx.x;
    sm[threadIdx.x] = (idx < N_NODES) ? g_cnt[idx] : 0;
    __syncthreads();
    for (int s = SCAN_B / 2; s > 0; s >>= 1) {
        if (threadIdx.x < s) sm[threadIdx.x] += sm[threadIdx.x + s];
        __syncthreads();
    }
    if (threadIdx.x == 0) g_part[blockIdx.x] = sm[0];
}

__global__ void scan_part_kernel() {           // exclusive scan of g_part
    __shared__ int sm[256];
    int t = threadIdx.x;
    sm[t] = (t < NB_SCAN) ? g_part[t] : 0;
    __syncthreads();
    if (t == 0) {
        int run = 0;
        for (int k = 0; k < NB_SCAN; k++) { int c = sm[k]; sm[k] = run; run += c; }
    }
    __syncthreads();
    if (t < NB_SCAN) g_part[t] = sm[t];
}

__global__ void scan_final_kernel() {          // exclusive scan of g_cnt -> g_off, g_pos
    __shared__ int sm[SCAN_B];
    int idx = blockIdx.x * SCAN_B + threadIdx.x;
    int x = (idx < N_NODES) ? g_cnt[idx] : 0;
    sm[threadIdx.x] = x;
    __syncthreads();
    for (int o = 1; o < SCAN_B; o <<= 1) {     // inclusive Hillis-Steele
        int t = (threadIdx.x >= o) ? sm[threadIdx.x - o] : 0;
        __syncthreads();
        sm[threadIdx.x] += t;
        __syncthreads();
    }
    if (idx < N_NODES) {
        int excl = sm[threadIdx.x] - x + g_part[blockIdx.x];
        g_off[idx] = excl;
        g_pos[idx] = excl;
    }
}

__global__ void scatter_kernel(const int* __restrict__ src,
                               const int* __restrict__ dst,
                               const float* __restrict__ val) {
    int e = blockIdx.x * blockDim.x + threadIdx.x;
    if (e < N_EDGES) {
        int p = atomicAdd(&g_pos[dst[e]], 1);
        g_edges[p] = make_int2(src[e], __float_as_int(val[e]));
    }
}

// ---------------------------------------------------------------------------
// CSR SpMM: one warp per destination node, float2 per lane (64 floats / 32).
// Edges consumed 32 per batch: each lane loads one (src,val) int2, broadcast
// via shfl. Accumulation in registers -> no atomics, no pre-zeroing.
// Epilogue folds acc update (and final *0.25).
// ---------------------------------------------------------------------------
template<bool WRITE_HN, bool FINAL>
__global__ void spmm_csr_kernel(const float* __restrict__ h,
                                float* __restrict__ hn,
                                float* __restrict__ acc) {
    int warp = (int)((blockIdx.x * blockDim.x + threadIdx.x) >> 5);
    int lane = threadIdx.x & 31;
    if (warp >= N_NODES) return;

    int start = g_off[warp];
    int n     = g_cnt[warp];
    const float2* __restrict__ hp = (const float2*)h;

    float2 s = make_float2(0.f, 0.f);
    int i = 0;
    for (; i + 32 <= n; i += 32) {
        int2 ed = __ldg(&g_edges[start + i + lane]);
        #pragma unroll 8
        for (int j = 0; j < 32; j++) {
            int   sj = __shfl_sync(0xffffffffu, ed.x, j);
            float vj = __int_as_float(__shfl_sync(0xffffffffu, ed.y, j));
            float2 x = __ldg(hp + (size_t)sj * 32 + lane);
            s.x += vj * x.x;
            s.y += vj * x.y;
        }
    }
    int rem = n - i;
    if (rem > 0) {
        int2 ed = (lane < rem) ? __ldg(&g_edges[start + i + lane]) : make_int2(0, 0);
        for (int j = 0; j < rem; j++) {
            int   sj = __shfl_sync(0xffffffffu, ed.x, j);
            float vj = __int_as_float(__shfl_sync(0xffffffffu, ed.y, j));
            float2 x = __ldg(hp + (size_t)sj * 32 + lane);
            s.x += vj * x.x;
            s.y += vj * x.y;
        }
    }

    size_t o = (size_t)warp * 32 + lane;       // float2 index
    if (WRITE_HN) ((float2*)hn)[o] = s;
    float2 a = ((float2*)acc)[o];
    if (FINAL) {
        a.x = (a.x + s.x) * 0.25f;
        a.y = (a.y + s.y) * 0.25f;
    } else {
        a.x += s.x;
        a.y += s.y;
    }
    ((float2*)acc)[o] = a;
}

// ---------------------------------------------------------------------------
extern "C" void kernel_launch(void* const* d_in, const int* in_sizes, int n_in,
                              void* d_out, int out_size) {
    const float* user_emb = (const float*)d_in[0];
    const float* item_emb = (const float*)d_in[1];
    const int*   edge_src = (const int*)d_in[2];
    const int*   edge_dst = (const int*)d_in[3];
    const float* edge_val = (const float*)d_in[4];
    float* acc = (float*)d_out;

    float *h, *hn;
    cudaGetSymbolAddress((void**)&h,  g_h);
    cudaGetSymbolAddress((void**)&hn, g_hn);

    const int TB = 256;
    const int grid_elem = (int)((N_ELEMS / 4 + TB - 1) / TB);      // covers N_NODES too
    const int grid_edge = (N_EDGES + TB - 1) / TB;
    const int grid_spmm = (N_NODES * 32 + TB - 1) / TB;            // 1 warp / node

    // init h & acc, zero degree counters
    init_kernel<<<grid_elem, TB>>>(user_emb, item_emb, h, acc);

    // CSR build (reused by all 3 layers)
    hist_kernel<<<grid_edge, TB>>>(edge_dst);
    block_reduce_kernel<<<NB_SCAN, SCAN_B>>>();
    scan_part_kernel<<<1, 256>>>();
    scan_final_kernel<<<NB_SCAN, SCAN_B>>>();
    scatter_kernel<<<grid_edge, TB>>>(edge_src, edge_dst, edge_val);

    // Layer 1: h -> hn, acc += hn
    spmm_csr_kernel<true, false><<<grid_spmm, TB>>>(h, hn, acc);
    // Layer 2: hn -> h, acc += h
    spmm_csr_kernel<true, false><<<grid_spmm, TB>>>(hn, h, acc);
    // Layer 3: h -> (discard), acc = (acc + sum) * 0.25
    spmm_csr_kernel<false, true><<<grid_spmm, TB>>>(h, nullptr, acc);
}

// round 5
// speedup vs baseline: 2.8690x; 1.9473x over previous
#include <cuda_runtime.h>
#include <cuda_fp16.h>
#include <cstdint>

#define N_USERS 100000
#define M_ITEMS 50000
#define N_NODES (N_USERS + M_ITEMS)        // 150000
#define N_EDGES 6000000
#define DIM 64
#define ROW_H2 (DIM / 2)                   // 32 half2 per node row
#define N_H2 ((size_t)N_NODES * ROW_H2)    // 4,800,000 half2

#define SCAN_B 1024
#define NB_SCAN ((N_NODES + SCAN_B - 1) / SCAN_B)   // 147

// ---- static scratch (no allocation allowed) --------------------------------
__device__ __half2 g_b0[N_H2];       // 19.2 MB  h after 0 hops (quantized input)
__device__ __half2 g_b1[N_H2];       // 19.2 MB  h after 1 hop
__device__ __half2 g_b2[N_H2];       // 19.2 MB  h after 2 hops
__device__ int2    g_edges[N_EDGES]; // 48 MB    (src*32, val_bits) sorted by dst
__device__ int     g_cnt[N_NODES];
__device__ int     g_off[N_NODES];
__device__ int     g_pos[N_NODES];
__device__ int     g_part[NB_SCAN];

// ---------------------------------------------------------------------------
// init: b0 = fp16(concat(user_emb, item_emb)); zero degree counters
// ---------------------------------------------------------------------------
__global__ void init_kernel(const float* __restrict__ user_emb,
                            const float* __restrict__ item_emb) {
    size_t i = (size_t)blockIdx.x * blockDim.x + threadIdx.x;   // half2 index
    if (i < N_H2) {
        size_t user2 = (size_t)N_USERS * ROW_H2;
        float2 v = (i < user2) ? ((const float2*)user_emb)[i]
                               : ((const float2*)item_emb)[i - user2];
        g_b0[i] = __floats2half2_rn(v.x, v.y);
    }
    if (i < N_NODES) g_cnt[i] = 0;
}

// ---------------------------------------------------------------------------
// CSR build
// ---------------------------------------------------------------------------
__global__ void hist_kernel(const int* __restrict__ dst) {
    int e = blockIdx.x * blockDim.x + threadIdx.x;
    if (e < N_EDGES) atomicAdd(&g_cnt[dst[e]], 1);
}

__global__ void block_reduce_kernel() {        // g_cnt -> g_part[b]
    __shared__ int sm[SCAN_B];
    int idx = blockIdx.x * SCAN_B + threadIdx.x;
    sm[threadIdx.x] = (idx < N_NODES) ? g_cnt[idx] : 0;
    __syncthreads();
    for (int s = SCAN_B / 2; s > 0; s >>= 1) {
        if (threadIdx.x < s) sm[threadIdx.x] += sm[threadIdx.x + s];
        __syncthreads();
    }
    if (threadIdx.x == 0) g_part[blockIdx.x] = sm[0];
}

__global__ void scan_part_kernel() {           // exclusive scan of g_part
    __shared__ int sm[256];
    int t = threadIdx.x;
    sm[t] = (t < NB_SCAN) ? g_part[t] : 0;
    __syncthreads();
    if (t == 0) {
        int run = 0;
        for (int k = 0; k < NB_SCAN; k++) { int c = sm[k]; sm[k] = run; run += c; }
    }
    __syncthreads();
    if (t < NB_SCAN) g_part[t] = sm[t];
}

__global__ void scan_final_kernel() {          // exclusive scan -> g_off, g_pos
    __shared__ int sm[SCAN_B];
    int idx = blockIdx.x * SCAN_B + threadIdx.x;
    int x = (idx < N_NODES) ? g_cnt[idx] : 0;
    sm[threadIdx.x] = x;
    __syncthreads();
    for (int o = 1; o < SCAN_B; o <<= 1) {     // inclusive Hillis-Steele
        int t = (threadIdx.x >= o) ? sm[threadIdx.x - o] : 0;
        __syncthreads();
        sm[threadIdx.x] += t;
        __syncthreads();
    }
    if (idx < N_NODES) {
        int excl = sm[threadIdx.x] - x + g_part[blockIdx.x];
        g_off[idx] = excl;
        g_pos[idx] = excl;
    }
}

__global__ void scatter_kernel(const int* __restrict__ src,
                               const int* __restrict__ dst,
                               const float* __restrict__ val) {
    int e = blockIdx.x * blockDim.x + threadIdx.x;
    if (e < N_EDGES) {
        int p = atomicAdd(&g_pos[dst[e]], 1);
        // pre-bake src row offset in half2 units (src * 32)
        g_edges[p] = make_int2(src[e] * ROW_H2, __float_as_int(val[e]));
    }
}

// ---------------------------------------------------------------------------
// CSR SpMM: one warp per destination node, one half2 (2 dims) per lane.
// Edge batches of 32 staged through smem (LDS.64 broadcast, conflict-free).
// f32 accumulation in registers. FINAL fuses out = (b0+b1+b2+h3)*0.25 in f32.
// ---------------------------------------------------------------------------
template<bool FINAL>
__global__ void spmm_csr_kernel(const __half2* __restrict__ hin,
                                __half2* __restrict__ hout,
                                float* __restrict__ out) {
    __shared__ int2 sm_ed[8][32];
    int wl   = threadIdx.x >> 5;
    int node = blockIdx.x * (blockDim.x >> 5) + wl;
    int lane = threadIdx.x & 31;
    if (node >= N_NODES) return;

    int start = g_off[node];
    int n     = g_cnt[node];

    float2 s = make_float2(0.f, 0.f);
    int i = 0;
    for (; i + 32 <= n; i += 32) {
        sm_ed[wl][lane] = __ldg(&g_edges[start + i + lane]);
        __syncwarp();
        #pragma unroll 8
        for (int j = 0; j < 32; j++) {
            int2 e = sm_ed[wl][j];
            float  v = __int_as_float(e.y);
            float2 x = __half22float2(__ldg(&hin[e.x + lane]));
            s.x += v * x.x;
            s.y += v * x.y;
        }
        __syncwarp();
    }
    int rem = n - i;
    if (rem > 0) {
        int2 ed = make_int2(0, 0);
        if (lane < rem) ed = __ldg(&g_edges[start + i + lane]);
        sm_ed[wl][lane] = ed;
        __syncwarp();
        for (int j = 0; j < rem; j++) {
            int2 e = sm_ed[wl][j];
            float  v = __int_as_float(e.y);
            float2 x = __half22float2(__ldg(&hin[e.x + lane]));
            s.x += v * x.x;
            s.y += v * x.y;
        }
    }

    size_t o = (size_t)node * ROW_H2 + lane;
    if (!FINAL) {
        hout[o] = __floats2half2_rn(s.x, s.y);
    } else {
        float2 a0 = __half22float2(g_b0[o]);
        float2 a1 = __half22float2(g_b1[o]);
        float2 a2 = __half22float2(hin[o]);   // hin == g_b2 in the final layer
        float2 r;
        r.x = (a0.x + a1.x + a2.x + s.x) * 0.25f;
        r.y = (a0.y + a1.y + a2.y + s.y) * 0.25f;
        ((float2*)out)[o] = r;
    }
}

// ---------------------------------------------------------------------------
extern "C" void kernel_launch(void* const* d_in, const int* in_sizes, int n_in,
                              void* d_out, int out_size) {
    const float* user_emb = (const float*)d_in[0];
    const float* item_emb = (const float*)d_in[1];
    const int*   edge_src = (const int*)d_in[2];
    const int*   edge_dst = (const int*)d_in[3];
    const float* edge_val = (const float*)d_in[4];
    float* out = (float*)d_out;

    __half2 *b0, *b1, *b2;
    cudaGetSymbolAddress((void**)&b0, g_b0);
    cudaGetSymbolAddress((void**)&b1, g_b1);
    cudaGetSymbolAddress((void**)&b2, g_b2);

    const int TB = 256;
    const int grid_init = (int)((N_H2 + TB - 1) / TB);             // covers N_NODES too
    const int grid_edge = (N_EDGES + TB - 1) / TB;
    const int grid_spmm = (N_NODES * 32 + TB - 1) / TB;            // 1 warp / node

    init_kernel<<<grid_init, TB>>>(user_emb, item_emb);

    // CSR build (reused by all 3 layers)
    hist_kernel<<<grid_edge, TB>>>(edge_dst);
    block_reduce_kernel<<<NB_SCAN, SCAN_B>>>();
    scan_part_kernel<<<1, 256>>>();
    scan_final_kernel<<<NB_SCAN, SCAN_B>>>();
    scatter_kernel<<<grid_edge, TB>>>(edge_src, edge_dst, edge_val);

    // Layer 1: b0 -> b1
    spmm_csr_kernel<false><<<grid_spmm, TB>>>(b0, b1, nullptr);
    // Layer 2: b1 -> b2
    spmm_csr_kernel<false><<<grid_spmm, TB>>>(b1, b2, nullptr);
    // Layer 3: b2 -> (h3 on the fly), out = (b0+b1+b2+h3) * 0.25
    spmm_csr_kernel<true><<<grid_spmm, TB>>>(b2, nullptr, out);
}